// round 2
// baseline (speedup 1.0000x reference)
#include <cuda_runtime.h>
#include <cstdint>

#define KNBR 16
#define F_IN 7
#define F_HID 40
#define F_OUT 3
#define MSG_PER_THREAD 4        // threads per node = 4
#define BLOCK 256

// ---- f32x2 packed helpers (sm_103a; ptxas never auto-fuses, must be PTX) ----
__device__ __forceinline__ unsigned long long pack2(float lo, float hi) {
    unsigned long long r;
    asm("mov.b64 %0, {%1, %2};" : "=l"(r) : "f"(lo), "f"(hi));
    return r;
}
__device__ __forceinline__ unsigned long long fma2(unsigned long long a,
                                                   unsigned long long b,
                                                   unsigned long long c) {
    unsigned long long d;
    asm("fma.rn.f32x2 %0, %1, %2, %3;" : "=l"(d) : "l"(a), "l"(b), "l"(c));
    return d;
}
__device__ __forceinline__ void unpack2(unsigned long long v, float& lo, float& hi) {
    asm("mov.b64 {%0, %1}, %2;" : "=f"(lo), "=f"(hi) : "l"(v));
}

__global__ __launch_bounds__(BLOCK, 4)
void aggre_mlp_kernel(const float* __restrict__ mailbox,
                      const float* __restrict__ W1,
                      const float* __restrict__ b1,
                      const float* __restrict__ W2,
                      const float* __restrict__ b2,
                      float* __restrict__ out,
                      int n_nodes) {
    // Per-hidden-unit row: 8 float2 (64B, 16B-aligned): [wdup0..wdup6, biasdup].
    // Duplicated halves let packed-message fma2 use a direct ld.shared.b64 operand.
    __shared__ __align__(16) float2 s_w1dup[F_HID][8];
    // Layer-2 row per h: {W2[h][0], W2[h][1], W2[h][2], 0} -> one LDS.128.
    __shared__ __align__(16) float4 s_w2q[F_HID];
    __shared__ float s_b2[F_OUT];

    const int tid = threadIdx.x;
    for (int i = tid; i < F_HID * 8; i += BLOCK) {
        int h = i >> 3, s = i & 7;
        float v = (s < F_IN) ? W1[s * F_HID + h] : b1[h];
        s_w1dup[h][s] = make_float2(v, v);
    }
    for (int h = tid; h < F_HID; h += BLOCK)
        s_w2q[h] = make_float4(W2[h * F_OUT + 0], W2[h * F_OUT + 1],
                               W2[h * F_OUT + 2], 0.f);
    if (tid < F_OUT) s_b2[tid] = b2[tid];
    __syncthreads();

    const long long gt = (long long)blockIdx.x * BLOCK + tid;
    const long long total = (long long)n_nodes * (KNBR / MSG_PER_THREAD);
    if (gt >= total) return;

    const long long node = gt >> 2;           // 4 threads per node
    const int sub = (int)(gt & 3);

    // 4 messages * 7 floats = 112B contiguous, 16B-aligned (112 = 7*16).
    const float4* src = reinterpret_cast<const float4*>(
        mailbox + (node * KNBR + (long long)sub * MSG_PER_THREAD) * F_IN);

    float m[28];
    #pragma unroll
    for (int i = 0; i < 7; i++) {
        float4 v = src[i];
        m[i * 4 + 0] = v.x; m[i * 4 + 1] = v.y;
        m[i * 4 + 2] = v.z; m[i * 4 + 3] = v.w;
    }
    // Pack across messages: mp01[f] = (msg0[f], msg1[f]), mp23[f] = (msg2[f], msg3[f]).
    unsigned long long mp01[F_IN], mp23[F_IN];
    #pragma unroll
    for (int f = 0; f < F_IN; f++) {
        mp01[f] = pack2(m[f],      m[7 + f]);
        mp23[f] = pack2(m[14 + f], m[21 + f]);
    }

    unsigned long long y01 = pack2(0.f, 0.f);
    float y2 = 0.f;

    #pragma unroll 4
    for (int h = 0; h < F_HID; h++) {
        const ulonglong2* wrow = reinterpret_cast<const ulonglong2*>(&s_w1dup[h][0]);
        ulonglong2 q0 = wrow[0];   // (w0dup, w1dup)
        ulonglong2 q1 = wrow[1];   // (w2dup, w3dup)
        ulonglong2 q2 = wrow[2];   // (w4dup, w5dup)
        ulonglong2 q3 = wrow[3];   // (w6dup, biasdup)

        unsigned long long a01 = q3.y, a23 = q3.y;
        a01 = fma2(mp01[0], q0.x, a01);  a23 = fma2(mp23[0], q0.x, a23);
        a01 = fma2(mp01[1], q0.y, a01);  a23 = fma2(mp23[1], q0.y, a23);
        a01 = fma2(mp01[2], q1.x, a01);  a23 = fma2(mp23[2], q1.x, a23);
        a01 = fma2(mp01[3], q1.y, a01);  a23 = fma2(mp23[3], q1.y, a23);
        a01 = fma2(mp01[4], q2.x, a01);  a23 = fma2(mp23[4], q2.x, a23);
        a01 = fma2(mp01[5], q2.y, a01);  a23 = fma2(mp23[5], q2.y, a23);
        a01 = fma2(mp01[6], q3.x, a01);  a23 = fma2(mp23[6], q3.x, a23);

        float r0, r1, r2, r3;
        unpack2(a01, r0, r1);
        unpack2(a23, r2, r3);
        float hs = (fmaxf(r0, 0.f) + fmaxf(r1, 0.f))
                 + (fmaxf(r2, 0.f) + fmaxf(r3, 0.f));

        // Layer 2 folded through the mean: y += hs * W2[h][:]
        ulonglong2 w2v = *reinterpret_cast<const ulonglong2*>(&s_w2q[h]);
        y01 = fma2(pack2(hs, hs), w2v.x, y01);
        float w22, w2pad;
        unpack2(w2v.y, w22, w2pad);
        y2 = fmaf(hs, w22, y2);
    }

    float y0, y1;
    unpack2(y01, y0, y1);

    // Reduce over the 4 sibling lanes of this node (adjacent lanes).
    #pragma unroll
    for (int d = 1; d < MSG_PER_THREAD; d <<= 1) {
        y0 += __shfl_xor_sync(0xffffffffu, y0, d);
        y1 += __shfl_xor_sync(0xffffffffu, y1, d);
        y2 += __shfl_xor_sync(0xffffffffu, y2, d);
    }

    // Lanes sub=0..2 each store one output component (semi-coalesced).
    if (sub < F_OUT) {
        const float inv = 1.0f / (float)KNBR;
        float v = (sub == 0) ? y0 : (sub == 1) ? y1 : y2;
        out[node * F_OUT + sub] = v * inv + s_b2[sub];
    }
}

extern "C" void kernel_launch(void* const* d_in, const int* in_sizes, int n_in,
                              void* d_out, int out_size) {
    const float* mailbox = (const float*)d_in[0];
    const float* W1      = (const float*)d_in[1];
    const float* b1      = (const float*)d_in[2];
    const float* W2      = (const float*)d_in[3];
    const float* b2      = (const float*)d_in[4];
    float* out = (float*)d_out;

    const int n_nodes = in_sizes[0] / (KNBR * F_IN);
    const long long total_threads = (long long)n_nodes * (KNBR / MSG_PER_THREAD);
    const int blocks = (int)((total_threads + BLOCK - 1) / BLOCK);

    aggre_mlp_kernel<<<blocks, BLOCK>>>(mailbox, W1, b1, W2, b2, out, n_nodes);
}